// round 5
// baseline (speedup 1.0000x reference)
#include <cuda_runtime.h>
#include <cstdint>
#include <cstddef>

#define T_STEPS 2048
#define BATCH   64
#define DIM     256
#define UNITS   512
#define PCOLS   1536     // 2U (xz) + U (xu)
#define ROWPAD  516      // 512 + 4 pad floats (16B-aligned rows, conflict-free LDS.128)
#define N_CG    16       // column groups
#define N_BG    8        // batch groups
#define BLOC    8        // batches per group

typedef unsigned long long u64_t;

// ---------------- scratch ----------------------------------------------------------
__device__ float    g_P[(size_t)T_STEPS * PCOLS * BATCH];   // [t][col][batch] fp32
// g_h2 / g_hr2: pair-interleaved K-split layout per batch:
//   g_h2[b*512 + 2*kp + s] = h_b[kp + s*256],  kp in [0,256), s in {0,1}
__device__ float    g_h2 [BATCH * UNITS];
__device__ float    g_hr2[BATCH * UNITS];
__device__ float    g_zt [BATCH * UNITS];    // plain [b][u]
__device__ unsigned g_bar[N_BG];

static __device__ __forceinline__ float sigmoidf_(float z) {
    return 1.0f / (1.0f + __expf(-z));
}

// packed fp32x2 FMA (Blackwell FFMA2 — 2 exact fp32 FMAs per lane, rt=2)
static __device__ __forceinline__ u64_t ffma2_(u64_t a, u64_t b, u64_t c) {
    u64_t d;
    asm("fma.rn.f32x2 %0, %1, %2, %3;" : "=l"(d) : "l"(a), "l"(b), "l"(c));
    return d;
}
static __device__ __forceinline__ float psum_(u64_t p) {
    union { u64_t u; float2 f; } v; v.u = p;
    return v.f.x + v.f.y;
}
// slot of logical unit u in the pair-interleaved layout
static __device__ __forceinline__ int kslot_(int u) {
    return (u < 256) ? (2 * u) : (2 * (u - 256) + 1);
}

// ---------------- init: zero h0 and barrier counters every launch ------------------
__global__ void gru_init() {
    int i = blockIdx.x * blockDim.x + threadIdx.x;
    if (i < BATCH * UNITS) g_h2[i] = 0.0f;
    if (i < N_BG) g_bar[i] = 0u;
}

// ---------------- projection GEMM: P[t][c][b] = sum_d x[b][t][d] * W[d][c] --------
__global__ void __launch_bounds__(256, 1)
gru_proj(const float* __restrict__ x, const float* __restrict__ Wk,
         const float* __restrict__ Wu) {
    extern __shared__ float sm[];
    float* xs = sm;               // [64][260]
    float* ws = sm + 64 * 260;    // [256][128]

    const int tid = threadIdx.x;
    const int t   = blockIdx.y;
    const int c0  = blockIdx.x * 128;

    const float* Wsrc;
    int ldw, cbase;
    if (c0 < 2 * UNITS) { Wsrc = Wk; ldw = 2 * UNITS; cbase = c0; }
    else                { Wsrc = Wu; ldw = UNITS;     cbase = c0 - 2 * UNITS; }

    for (int i = tid; i < 64 * 64; i += 256) {
        int b = i >> 6, dq = i & 63;
        float4 v = *(const float4*)(x + ((size_t)b * T_STEPS + t) * DIM + dq * 4);
        *(float4*)(xs + b * 260 + dq * 4) = v;
    }
    for (int i = tid; i < 256 * 32; i += 256) {
        int d = i >> 5, cq = i & 31;
        float4 v = *(const float4*)(Wsrc + (size_t)d * ldw + cbase + cq * 4);
        *(float4*)(ws + d * 128 + cq * 4) = v;
    }
    __syncthreads();

    const int q  = tid & 15;
    const int cb = (tid >> 4) * 8;

    float acc[4][8];
#pragma unroll
    for (int i = 0; i < 4; ++i)
#pragma unroll
        for (int j = 0; j < 8; ++j) acc[i][j] = 0.0f;

#pragma unroll 4
    for (int k = 0; k < 256; ++k) {
        float xv[4];
#pragma unroll
        for (int i = 0; i < 4; ++i) xv[i] = xs[(q * 4 + i) * 260 + k];
        float4 w0 = *(const float4*)(ws + k * 128 + cb);
        float4 w1 = *(const float4*)(ws + k * 128 + cb + 4);
        float wv[8] = { w0.x, w0.y, w0.z, w0.w, w1.x, w1.y, w1.z, w1.w };
#pragma unroll
        for (int i = 0; i < 4; ++i)
#pragma unroll
            for (int j = 0; j < 8; ++j)
                acc[i][j] = fmaf(xv[i], wv[j], acc[i][j]);
    }

    float* outp = g_P + ((size_t)t * PCOLS + c0 + cb) * BATCH + q * 4;
#pragma unroll
    for (int j = 0; j < 8; ++j) {
        float4 v = make_float4(acc[0][j], acc[1][j], acc[2][j], acc[3][j]);
        __stcs((float4*)(outp + (size_t)j * BATCH), v);
    }
}

// ---------------- batch-group barrier (16 CTAs per counter, monotone) --------------
static __device__ __forceinline__ void bg_barrier(unsigned* ctr, unsigned target) {
    __threadfence();          // release: order prior global stores
    __syncthreads();
    if (threadIdx.x == 0) {
        atomicAdd(ctr, 1u);
        volatile unsigned* vc = ctr;
        while (*vc < target) { __nanosleep(20); }
        __threadfence();      // acquire: order subsequent reads
    }
    __syncthreads();
}

// ---------------- persistent recurrence kernel ------------------------------------
__global__ void __launch_bounds__(256, 1)
gru_rec(const float* __restrict__ Wrk, const float* __restrict__ brk,
        const float* __restrict__ Wur, const float* __restrict__ bur,
        float* __restrict__ out) {
    extern __shared__ float sm[];
    float* WrkS = sm;                    // [64][516] pair-interleaved K-split rows
    float* WurS = sm + 64 * ROWPAD;      // [32][516] same
    float* HS   = sm + 96 * ROWPAD;      // [8][516]  staged h/hr (already paired)

    const int tid = threadIdx.x;
    const int cg  = blockIdx.x & 15;
    const int bg  = blockIdx.x >> 4;

    // weight slices, pair-interleaved: row c holds {W[kp][c], W[kp+256][c]} pairs
    for (int i = tid; i < 64 * 256; i += 256) {
        int kp = i >> 6, c = i & 63;
        int col = cg * 64 + c;
        WrkS[c * ROWPAD + 2 * kp]     = Wrk[(size_t)kp * (2 * UNITS) + col];
        WrkS[c * ROWPAD + 2 * kp + 1] = Wrk[(size_t)(kp + 256) * (2 * UNITS) + col];
    }
    for (int i = tid; i < 32 * 256; i += 256) {
        int kp = i >> 5, c = i & 31;
        int col = cg * 32 + c;
        WurS[c * ROWPAD + 2 * kp]     = Wur[(size_t)kp * UNITS + col];
        WurS[c * ROWPAD + 2 * kp + 1] = Wur[(size_t)(kp + 256) * UNITS + col];
    }

    // phase-A mapping: 64 cols x 4 batch-pairs
    const int cA    = tid & 63;
    const int bh    = tid >> 6;
    const int jglob = cg * 64 + cA;            // z column 0..1023
    const float brkv = brk[jglob];
    const int b0    = bg * BLOC + 2 * bh;
    const int slotA = (jglob < UNITS) ? kslot_(jglob) : 0;  // cg-uniform when used

    // phase-B mapping: 32 cols x 8 batches
    const int cB    = tid & 31;
    const int bB    = tid >> 5;
    const int uglob = cg * 32 + cB;
    const float burv = bur[uglob];
    const int bPB   = bg * BLOC + bB;
    const int slotB = kslot_(uglob);           // cg-uniform

    unsigned* ctr = &g_bar[bg];
    unsigned target = 0;

    const float* pA = g_P + (size_t)jglob * BATCH + b0;
    const float* pB = g_P + (size_t)(2 * UNITS + uglob) * BATCH + bPB;
    const size_t pstride = (size_t)PCOLS * BATCH;

    __syncthreads();

    float2 xz = __ldcs((const float2*)pA);     // prefetch step-0 xz

    for (int t = 0; t < T_STEPS; ++t) {
        // ---- stage h (already pair-interleaved) ----
        for (int i = tid; i < BLOC * 128; i += 256) {
            int b = i >> 7, kq = i & 127;
            float4 v = __ldcg((const float4*)&g_h2[(size_t)(bg * BLOC + b) * UNITS + kq * 4]);
            *(float4*)&HS[b * ROWPAD + kq * 4] = v;
        }
        __syncthreads();

        // ---- phase A: z[b, jglob] = xz + h . Wrk[:,jglob]  (FFMA2 K-split) ----
        {
            const ulonglong2* wr  = (const ulonglong2*)(WrkS + cA * ROWPAD);
            const ulonglong2* h0p = (const ulonglong2*)(HS + (2 * bh) * ROWPAD);
            const ulonglong2* h1p = (const ulonglong2*)(HS + (2 * bh + 1) * ROWPAD);
            u64_t a0 = 0, a1 = 0, b0a = 0, b1a = 0;   // packed {lo-half, hi-half} sums
#pragma unroll 8
            for (int i = 0; i < 128; ++i) {
                ulonglong2 w = wr[i];
                ulonglong2 p = h0p[i];
                ulonglong2 r = h1p[i];
                a0  = ffma2_(w.x, p.x, a0);  a1  = ffma2_(w.y, p.y, a1);
                b0a = ffma2_(w.x, r.x, b0a); b1a = ffma2_(w.y, r.y, b1a);
            }
            float z0 = psum_(a0)  + psum_(a1)  + xz.x + brkv;
            float z1 = psum_(b0a) + psum_(b1a) + xz.y + brkv;
            if (jglob < UNITS) {            // r-gate -> write h*r (paired layout)
                float r0 = sigmoidf_(z0), r1 = sigmoidf_(z1);
                float hv0 = HS[(2 * bh) * ROWPAD + slotA];
                float hv1 = HS[(2 * bh + 1) * ROWPAD + slotA];
                __stcg(&g_hr2[(size_t)b0 * UNITS + slotA], hv0 * r0);
                __stcg(&g_hr2[(size_t)(b0 + 1) * UNITS + slotA], hv1 * r1);
            } else {                        // update gate -> z_t (plain layout)
                int u = jglob - UNITS;
                __stcg(&g_zt[(size_t)b0 * UNITS + u], sigmoidf_(z0));
                __stcg(&g_zt[(size_t)(b0 + 1) * UNITS + u], sigmoidf_(z1));
            }
        }
        target += N_CG;
        bg_barrier(ctr, target);            // barrier 1: hr & zt complete

        // ---- stage hr (paired) + independent loads ----
        for (int i = tid; i < BLOC * 128; i += 256) {
            int b = i >> 7, kq = i & 127;
            float4 v = __ldcg((const float4*)&g_hr2[(size_t)(bg * BLOC + b) * UNITS + kq * 4]);
            *(float4*)&HS[b * ROWPAD + kq * 4] = v;
        }
        const float xu   = __ldcs(pB);
        const float ztv  = __ldcg(&g_zt[(size_t)bPB * UNITS + uglob]);
        const float hold = __ldcg(&g_h2[(size_t)bPB * UNITS + slotB]);
        __syncthreads();

        // prefetch next xz (overlaps phase-B math)
        pA += pstride;
        if (t + 1 < T_STEPS) xz = __ldcs((const float2*)pA);

        // ---- phase B: ht = tanh(xu + hr . Wur[:,uglob] + bur); combine ----
        {
            const ulonglong2* wu = (const ulonglong2*)(WurS + cB * ROWPAD);
            const ulonglong2* hb = (const ulonglong2*)(HS + bB * ROWPAD);
            u64_t s0 = 0, s1 = 0;
#pragma unroll 8
            for (int i = 0; i < 128; ++i) {
                ulonglong2 w = wu[i];
                ulonglong2 h = hb[i];
                s0 = ffma2_(w.x, h.x, s0);
                s1 = ffma2_(w.y, h.y, s1);
            }
            float ht   = tanhf(psum_(s0) + psum_(s1) + xu + burv);
            float hnew = (1.0f - ztv) * hold + ztv * ht;
            __stcg(&g_h2[(size_t)bPB * UNITS + slotB], hnew);
            if (t == T_STEPS - 1)
                out[(size_t)bPB * UNITS + uglob] = hnew;   // plain layout
        }
        target += N_CG;
        bg_barrier(ctr, target);            // barrier 2: h updated

        pB += pstride;
    }
}

// ---------------- launch ----------------------------------------------------------
extern "C" void kernel_launch(void* const* d_in, const int* in_sizes, int n_in,
                              void* d_out, int out_size) {
    (void)in_sizes; (void)n_in; (void)out_size;
    const float* x   = (const float*)d_in[0];
    const float* Wk  = (const float*)d_in[1];
    const float* Wrk = (const float*)d_in[2];
    const float* brk = (const float*)d_in[3];
    const float* Wu  = (const float*)d_in[4];
    const float* Wur = (const float*)d_in[5];
    const float* bur = (const float*)d_in[6];
    float* out = (float*)d_out;

    const int smemProj = (64 * 260 + 256 * 128) * 4;   // 197632 B
    const int smemRec  = (104 * ROWPAD) * 4;           // 214656 B

    cudaFuncSetAttribute(gru_proj, cudaFuncAttributeMaxDynamicSharedMemorySize, smemProj);
    cudaFuncSetAttribute(gru_rec,  cudaFuncAttributeMaxDynamicSharedMemorySize, smemRec);

    gru_init<<<128, 256>>>();
    gru_proj<<<dim3(12, T_STEPS), 256, smemProj>>>(x, Wk, Wu);
    gru_rec<<<128, 256, smemRec>>>(Wrk, brk, Wur, bur, out);
}

// round 8
// speedup vs baseline: 1.0991x; 1.0991x over previous
#include <cuda_runtime.h>
#include <cstdint>
#include <cstddef>

#define T_STEPS 2048
#define BATCH   64
#define DIM     256
#define UNITS   512
#define PCOLS   1536     // 2U (xz) + U (xu)
#define ROWPAD  516      // 512 + 4 pad floats (16B-aligned rows, conflict-free LDS.128)
#define N_CG    16       // column groups
#define N_BG    8        // batch groups
#define BLOC    8        // batches per group

typedef unsigned long long u64_t;

// ---------------- scratch ----------------------------------------------------------
__device__ float    g_P[(size_t)T_STEPS * PCOLS * BATCH];   // [t][col][batch] fp32
// g_h2 / g_hr2: pair-interleaved K-split layout per batch:
//   g_h2[b*512 + 2*kp + s] = h_b[kp + s*256],  kp in [0,256), s in {0,1}
__device__ float    g_h2 [BATCH * UNITS];
__device__ float    g_hr2[BATCH * UNITS];
__device__ float    g_zt [BATCH * UNITS];    // plain [b][u]
__device__ unsigned g_bar[N_BG * 32];        // one counter per 128-B line

static __device__ __forceinline__ float sigmoidf_(float z) {
    return 1.0f / (1.0f + __expf(-z));
}

// packed fp32x2 FMA (FFMA2 — 2 exact fp32 FMAs per lane, rt=2)
static __device__ __forceinline__ u64_t ffma2_(u64_t a, u64_t b, u64_t c) {
    u64_t d;
    asm("fma.rn.f32x2 %0, %1, %2, %3;" : "=l"(d) : "l"(a), "l"(b), "l"(c));
    return d;
}
static __device__ __forceinline__ float psum_(u64_t p) {
    union { u64_t u; float2 f; } v; v.u = p;
    return v.f.x + v.f.y;
}
// slot of logical unit u in the pair-interleaved layout
static __device__ __forceinline__ int kslot_(int u) {
    return (u < 256) ? (2 * u) : (2 * (u - 256) + 1);
}

// ---------------- init: zero h0 and barrier counters every launch ------------------
__global__ void gru_init() {
    int i = blockIdx.x * blockDim.x + threadIdx.x;
    if (i < BATCH * UNITS) g_h2[i] = 0.0f;
    if (i < N_BG * 32) g_bar[i] = 0u;
}

// ---------------- projection GEMM: P[t][c][b] = sum_d x[b][t][d] * W[d][c] --------
__global__ void __launch_bounds__(256, 1)
gru_proj(const float* __restrict__ x, const float* __restrict__ Wk,
         const float* __restrict__ Wu) {
    extern __shared__ float sm[];
    float* xs = sm;               // [64][260]
    float* ws = sm + 64 * 260;    // [256][128]

    const int tid = threadIdx.x;
    const int t   = blockIdx.y;
    const int c0  = blockIdx.x * 128;

    const float* Wsrc;
    int ldw, cbase;
    if (c0 < 2 * UNITS) { Wsrc = Wk; ldw = 2 * UNITS; cbase = c0; }
    else                { Wsrc = Wu; ldw = UNITS;     cbase = c0 - 2 * UNITS; }

    for (int i = tid; i < 64 * 64; i += 256) {
        int b = i >> 6, dq = i & 63;
        float4 v = *(const float4*)(x + ((size_t)b * T_STEPS + t) * DIM + dq * 4);
        *(float4*)(xs + b * 260 + dq * 4) = v;
    }
    for (int i = tid; i < 256 * 32; i += 256) {
        int d = i >> 5, cq = i & 31;
        float4 v = *(const float4*)(Wsrc + (size_t)d * ldw + cbase + cq * 4);
        *(float4*)(ws + d * 128 + cq * 4) = v;
    }
    __syncthreads();

    // broadcast-friendly mapping: xv is a 2-address broadcast, ws 2-way —
    // kills the previous 8-way xv bank conflict.
    const int q  = tid >> 4;        // batch quad 0..15
    const int cb = (tid & 15) * 8;  // 8 consecutive cols

    float acc[4][8];
#pragma unroll
    for (int i = 0; i < 4; ++i)
#pragma unroll
        for (int j = 0; j < 8; ++j) acc[i][j] = 0.0f;

#pragma unroll 4
    for (int k = 0; k < 256; ++k) {
        float xv[4];
#pragma unroll
        for (int i = 0; i < 4; ++i) xv[i] = xs[(q * 4 + i) * 260 + k];
        float4 w0 = *(const float4*)(ws + k * 128 + cb);
        float4 w1 = *(const float4*)(ws + k * 128 + cb + 4);
        float wv[8] = { w0.x, w0.y, w0.z, w0.w, w1.x, w1.y, w1.z, w1.w };
#pragma unroll
        for (int i = 0; i < 4; ++i)
#pragma unroll
            for (int j = 0; j < 8; ++j)
                acc[i][j] = fmaf(xv[i], wv[j], acc[i][j]);
    }

    float* outp = g_P + ((size_t)t * PCOLS + c0 + cb) * BATCH + q * 4;
#pragma unroll
    for (int j = 0; j < 8; ++j) {
        float4 v = make_float4(acc[0][j], acc[1][j], acc[2][j], acc[3][j]);
        __stcs((float4*)(outp + (size_t)j * BATCH), v);
    }
}

// ---------------- batch-group barrier: elected-thread acq/rel pattern --------------
// bar.sync; thread 0: release-red arrive, acquire-ld spin; bar.sync release.
// No MEMBAR.GPU anywhere — release/acquire + bar.sync HB edges give cumulativity.
static __device__ __forceinline__ void bg_barrier(unsigned* ctr, unsigned target) {
    __syncthreads();
    if (threadIdx.x == 0) {
        asm volatile("red.release.gpu.global.add.u32 [%0], %1;"
                     :: "l"(ctr), "r"(1u) : "memory");
        unsigned v;
        for (;;) {
            asm volatile("ld.acquire.gpu.global.u32 %0, [%1];"
                         : "=r"(v) : "l"(ctr) : "memory");
            if (v >= target) break;
            __nanosleep(20);
        }
    }
    __syncthreads();
}

// ---------------- persistent recurrence kernel ------------------------------------
__global__ void __launch_bounds__(256, 1)
gru_rec(const float* __restrict__ Wrk, const float* __restrict__ brk,
        const float* __restrict__ Wur, const float* __restrict__ bur,
        float* __restrict__ out) {
    extern __shared__ float sm[];
    float* WrkS = sm;                    // [64][516] pair-interleaved K-split rows
    float* WurS = sm + 64 * ROWPAD;      // [32][516] same
    float* HS   = sm + 96 * ROWPAD;      // [8][516]  staged h/hr (already paired)

    const int tid = threadIdx.x;
    const int cg  = blockIdx.x & 15;
    const int bg  = blockIdx.x >> 4;

    // weight slices, pair-interleaved: row c holds {W[kp][c], W[kp+256][c]} pairs
    for (int i = tid; i < 64 * 256; i += 256) {
        int kp = i >> 6, c = i & 63;
        int col = cg * 64 + c;
        WrkS[c * ROWPAD + 2 * kp]     = Wrk[(size_t)kp * (2 * UNITS) + col];
        WrkS[c * ROWPAD + 2 * kp + 1] = Wrk[(size_t)(kp + 256) * (2 * UNITS) + col];
    }
    for (int i = tid; i < 32 * 256; i += 256) {
        int kp = i >> 5, c = i & 31;
        int col = cg * 32 + c;
        WurS[c * ROWPAD + 2 * kp]     = Wur[(size_t)kp * UNITS + col];
        WurS[c * ROWPAD + 2 * kp + 1] = Wur[(size_t)(kp + 256) * UNITS + col];
    }

    // phase-A mapping: 64 cols x 4 batch-pairs
    const int cA    = tid & 63;
    const int bh    = tid >> 6;
    const int jglob = cg * 64 + cA;            // z column 0..1023
    const float brkv = brk[jglob];
    const int b0    = bg * BLOC + 2 * bh;
    const int slotA = (jglob < UNITS) ? kslot_(jglob) : 0;

    // phase-B mapping: 32 cols x 8 batches
    const int cB    = tid & 31;
    const int bB    = tid >> 5;
    const int uglob = cg * 32 + cB;
    const float burv = bur[uglob];
    const int bPB   = bg * BLOC + bB;
    const int slotB = kslot_(uglob);

    unsigned* ctr = &g_bar[bg * 32];
    unsigned target = 0;

    const float* pA = g_P + (size_t)jglob * BATCH + b0;
    const float* pB = g_P + (size_t)(2 * UNITS + uglob) * BATCH + bPB;
    const size_t pstride = (size_t)PCOLS * BATCH;

    __syncthreads();

    float2 xz = __ldcs((const float2*)pA);     // prefetch step-0 xz

    for (int t = 0; t < T_STEPS; ++t) {
        // ---- stage h (pair-interleaved) ----
        for (int i = tid; i < BLOC * 128; i += 256) {
            int b = i >> 7, kq = i & 127;
            float4 v = __ldcg((const float4*)&g_h2[(size_t)(bg * BLOC + b) * UNITS + kq * 4]);
            *(float4*)&HS[b * ROWPAD + kq * 4] = v;
        }
        __syncthreads();

        // ---- phase A: z[b, jglob] = xz + h . Wrk[:,jglob]  (FFMA2 K-split) ----
        {
            const ulonglong2* wr  = (const ulonglong2*)(WrkS + cA * ROWPAD);
            const ulonglong2* h0p = (const ulonglong2*)(HS + (2 * bh) * ROWPAD);
            const ulonglong2* h1p = (const ulonglong2*)(HS + (2 * bh + 1) * ROWPAD);
            u64_t a0 = 0, a1 = 0, b0a = 0, b1a = 0;
#pragma unroll 8
            for (int i = 0; i < 128; ++i) {
                ulonglong2 w = wr[i];
                ulonglong2 p = h0p[i];
                ulonglong2 r = h1p[i];
                a0  = ffma2_(w.x, p.x, a0);  a1  = ffma2_(w.y, p.y, a1);
                b0a = ffma2_(w.x, r.x, b0a); b1a = ffma2_(w.y, r.y, b1a);
            }
            float z0 = psum_(a0)  + psum_(a1)  + xz.x + brkv;
            float z1 = psum_(b0a) + psum_(b1a) + xz.y + brkv;
            if (jglob < UNITS) {            // r-gate -> write h*r (paired layout)
                float r0 = sigmoidf_(z0), r1 = sigmoidf_(z1);
                float hv0 = HS[(2 * bh) * ROWPAD + slotA];
                float hv1 = HS[(2 * bh + 1) * ROWPAD + slotA];
                __stcg(&g_hr2[(size_t)b0 * UNITS + slotA], hv0 * r0);
                __stcg(&g_hr2[(size_t)(b0 + 1) * UNITS + slotA], hv1 * r1);
            } else {                        // update gate -> z_t (plain layout)
                int u = jglob - UNITS;
                __stcg(&g_zt[(size_t)b0 * UNITS + u], sigmoidf_(z0));
                __stcg(&g_zt[(size_t)(b0 + 1) * UNITS + u], sigmoidf_(z1));
            }
        }

        // hold (h_old) from SMEM before HS is overwritten; xu prefetch (DRAM)
        // hides under the barrier spin.
        const float hold = HS[bB * ROWPAD + slotB];
        const float xu   = __ldcs(pB);

        target += N_CG;
        bg_barrier(ctr, target);            // barrier 1: hr & zt complete

        // ---- stage hr (paired) + dependent zt load ----
        for (int i = tid; i < BLOC * 128; i += 256) {
            int b = i >> 7, kq = i & 127;
            float4 v = __ldcg((const float4*)&g_hr2[(size_t)(bg * BLOC + b) * UNITS + kq * 4]);
            *(float4*)&HS[b * ROWPAD + kq * 4] = v;
        }
        const float ztv = __ldcg(&g_zt[(size_t)bPB * UNITS + uglob]);
        __syncthreads();

        // prefetch next xz (overlaps phase-B math)
        pA += pstride;
        if (t + 1 < T_STEPS) xz = __ldcs((const float2*)pA);

        // ---- phase B: ht = tanh(xu + hr . Wur[:,uglob] + bur); combine ----
        {
            const ulonglong2* wu = (const ulonglong2*)(WurS + cB * ROWPAD);
            const ulonglong2* hb = (const ulonglong2*)(HS + bB * ROWPAD);
            u64_t s0 = 0, s1 = 0;
#pragma unroll 8
            for (int i = 0; i < 128; ++i) {
                ulonglong2 w = wu[i];
                ulonglong2 h = hb[i];
                s0 = ffma2_(w.x, h.x, s0);
                s1 = ffma2_(w.y, h.y, s1);
            }
            float ht   = tanhf(psum_(s0) + psum_(s1) + xu + burv);
            float hnew = (1.0f - ztv) * hold + ztv * ht;
            __stcg(&g_h2[(size_t)bPB * UNITS + slotB], hnew);
            if (t == T_STEPS - 1)
                out[(size_t)bPB * UNITS + uglob] = hnew;   // plain layout
        }
        target += N_CG;
        bg_barrier(ctr, target);            // barrier 2: h updated

        pB += pstride;
    }
}

// ---------------- launch ----------------------------------------------------------
extern "C" void kernel_launch(void* const* d_in, const int* in_sizes, int n_in,
                              void* d_out, int out_size) {
    (void)in_sizes; (void)n_in; (void)out_size;
    const float* x   = (const float*)d_in[0];
    const float* Wk  = (const float*)d_in[1];
    const float* Wrk = (const float*)d_in[2];
    const float* brk = (const float*)d_in[3];
    const float* Wu  = (const float*)d_in[4];
    const float* Wur = (const float*)d_in[5];
    const float* bur = (const float*)d_in[6];
    float* out = (float*)d_out;

    const int smemProj = (64 * 260 + 256 * 128) * 4;   // 197632 B
    const int smemRec  = (104 * ROWPAD) * 4;           // 214656 B

    cudaFuncSetAttribute(gru_proj, cudaFuncAttributeMaxDynamicSharedMemorySize, smemProj);
    cudaFuncSetAttribute(gru_rec,  cudaFuncAttributeMaxDynamicSharedMemorySize, smemRec);

    gru_init<<<128, 256>>>();
    gru_proj<<<dim3(12, T_STEPS), 256, smemProj>>>(x, Wk, Wu);
    gru_rec<<<128, 256, smemRec>>>(Wrk, brk, Wur, bur, out);
}